// round 14
// baseline (speedup 1.0000x reference)
#include <cuda_runtime.h>
#include <cuda_fp16.h>
#include <cstdint>
#include <cstring>

#define THREADS 512
#define TM 128

#define S0  56    // A0 / W0 stride (halves) = 112B
#define S2  136   // A2 / W1 stride (halves) = 272B

// ---- smem byte layout: shared weights + per-group blocks (A0, A2, red, xs) ----
#define OFF_W0   0                       // 14336
#define OFF_W1   14336                   // 34816
#define GBASE    49152
#define GSTRIDE  51200                   // A0 14336 + A2 34816 + red 1024 + xs 1024
#define OFF_B0S  (GBASE + 2*GSTRIDE)     // 151552
#define OFF_B1S  (OFF_B0S + 512)
#define OFF_W2S  (OFF_B1S + 512)
#define OFF_XR0  (OFF_W2S + 512)         // W0 row 0 (fp32, 128)
#define OFF_XR1  (OFF_XR0 + 512)         // W0 row 1 (fp32, 128)
#define SMEM_BYTES (OFF_XR1 + 512)       // 154112

__device__ __forceinline__ uint32_t s2u(const void* p){
    uint32_t a;
    asm("{ .reg .u64 t; cvta.to.shared.u64 t, %1; cvt.u32.u64 %0, t; }" : "=r"(a) : "l"(p));
    return a;
}
__device__ __forceinline__ void ldsm4(uint32_t r[4], uint32_t addr){
    asm volatile("ldmatrix.sync.aligned.m8n8.x4.shared.b16 {%0,%1,%2,%3}, [%4];"
                 : "=r"(r[0]), "=r"(r[1]), "=r"(r[2]), "=r"(r[3]) : "r"(addr));
}
__device__ __forceinline__ void stsm4(uint32_t addr, uint32_t r0, uint32_t r1,
                                      uint32_t r2, uint32_t r3){
    asm volatile("stmatrix.sync.aligned.m8n8.x4.shared.b16 [%0], {%1,%2,%3,%4};"
                 :: "r"(addr), "r"(r0), "r"(r1), "r"(r2), "r"(r3) : "memory");
}
__device__ __forceinline__ void mma_f16(float c[4], const uint32_t a[4],
                                        uint32_t b0, uint32_t b1){
    asm volatile("mma.sync.aligned.m16n8k16.row.col.f32.f16.f16.f32 "
                 "{%0,%1,%2,%3}, {%4,%5,%6,%7}, {%8,%9}, {%0,%1,%2,%3};"
                 : "+f"(c[0]), "+f"(c[1]), "+f"(c[2]), "+f"(c[3])
                 : "r"(a[0]), "r"(a[1]), "r"(a[2]), "r"(a[3]), "r"(b0), "r"(b1));
}
__device__ __forceinline__ float clip01(float v){ return fminf(fmaxf(v, 0.f), 1.f); }
__device__ __forceinline__ uint32_t pk2(float a, float b){
    __half2 h = __floats2half2_rn(a, b);
    uint32_t u; memcpy(&u, &h, 4); return u;
}
// per-group named barrier (ids 1,2), 256 threads each
#define GBAR(g) asm volatile("bar.sync %0, 256;" :: "r"((g) + 1) : "memory")

// single-pass fp16 GEMM (layer 1)
template<int KS>
__device__ __forceinline__ void gemm1p(uint32_t aB0, uint32_t aB1,
                                       const uint32_t bB[4], float c[2][8][4]){
    #pragma unroll
    for (int ks = 0; ks < KS; ks++){
        uint32_t a0[4], a1[4], b[4][4];
        ldsm4(a0, aB0 + 32 * ks);
        ldsm4(a1, aB1 + 32 * ks);
        #pragma unroll
        for (int gg = 0; gg < 4; gg++) ldsm4(b[gg], bB[gg] + 32 * ks);
        #pragma unroll
        for (int ni = 0; ni < 8; ni++){
            uint32_t b0v = b[ni >> 1][(ni & 1) * 2];
            uint32_t b1v = b[ni >> 1][(ni & 1) * 2 + 1];
            mma_f16(c[0][ni], a0, b0v, b1v);
            mma_f16(c[1][ni], a1, b0v, b1v);
        }
    }
}

__global__ void __launch_bounds__(THREADS, 1)
mlp_xf_kernel(const float* __restrict__ x,
              const float* __restrict__ emb,
              const float* __restrict__ et,
              const float* __restrict__ W0,
              const float* __restrict__ b0,
              const float* __restrict__ W1,
              const float* __restrict__ b1,
              const float* __restrict__ W2,
              const float* __restrict__ b2,
              float* __restrict__ out,
              int Nq, int E, int ntiles)
{
    extern __shared__ __align__(1024) char smem[];
    const uint32_t sb = s2u(smem);
    const int tid = threadIdx.x;
    const int g   = tid >> 8;        // tile group 0/1
    const int t   = tid & 255;
    const int lane = t & 31, w = t >> 5;
    const int mw = w & 3, nw = w >> 2;

    const int a0off = GBASE + g * GSTRIDE;
    const int a2off = a0off + 14336;
    const int rdoff = a2off + 34816;
    const int xsoff = rdoff + 1024;

    // ---- zero W0 pad + both A0 buffers; load biases + W0 rows 0/1 ----
    for (int i = tid * 16; i < 14336; i += THREADS * 16){
        *(float4*)(smem + OFF_W0 + i) = make_float4(0.f, 0.f, 0.f, 0.f);
        *(float4*)(smem + GBASE + i) = make_float4(0.f, 0.f, 0.f, 0.f);
        *(float4*)(smem + GBASE + GSTRIDE + i) = make_float4(0.f, 0.f, 0.f, 0.f);
    }
    if (tid < 128){
        ((float*)(smem + OFF_B0S))[tid] = b0[tid];
        ((float*)(smem + OFF_B1S))[tid] = b1[tid];
        ((float*)(smem + OFF_W2S))[tid] = W2[tid];
        ((float*)(smem + OFF_XR0))[tid] = W0[tid];          // W0 row 0
        ((float*)(smem + OFF_XR1))[tid] = W0[128 + tid];    // W0 row 1
    }
    __syncthreads();

    // ---- stage W0^T fp16 (em rows 2..33 -> cols 0..31) ----
    for (int i = tid; i < 32 * 128; i += THREADS){
        int k = i >> 7, n = i & 127;
        *(__half*)(smem + OFF_W0 + (n * S0 + k) * 2) = __float2half_rn(W0[(k + 2) * 128 + n]);
    }
    // ---- stage W1^T fp16 ----
    for (int i = tid; i < 128 * 128; i += THREADS){
        int k = i >> 7, n = i & 127;
        *(__half*)(smem + OFF_W1 + (n * S2 + k) * 2) = __float2half_rn(W1[i]);
    }
    __syncthreads();

    const float b2v = __ldg(b2);
    const float* b0s = (const float*)(smem + OFF_B0S);
    const float* b1s = (const float*)(smem + OFF_B1S);
    const float* w2s = (const float*)(smem + OFF_W2S);
    const float* xr0 = (const float*)(smem + OFF_XR0);
    const float* xr1 = (const float*)(smem + OFF_XR1);
    float* red = (float*)(smem + rdoff);
    float2* xs = (float2*)(smem + xsoff);

    // ---- ldmatrix / stmatrix lane bases ----
    const uint32_t aB0 = sb + a0off + ((mw * 32 + (lane & 15)) * S0) * 2 + (lane >> 4) * 16;
    const uint32_t aB1 = aB0 + 16 * S0 * 2;
    const uint32_t a2B0 = sb + a2off + ((mw * 32 + (lane & 15)) * S2) * 2 + (lane >> 4) * 16;
    const uint32_t a2B1 = a2B0 + 16 * S2 * 2;
    const int nrow = (lane & 7) + ((lane >> 4) << 3);
    const int bko  = ((lane >> 3) & 1) * 16;
    uint32_t w0B[4], w1B[4];
    #pragma unroll
    for (int q = 0; q < 4; q++){
        w0B[q] = sb + OFF_W0 + ((nw * 64 + q * 16 + nrow) * S0) * 2 + bko;
        w1B[q] = sb + OFF_W1 + ((nw * 64 + q * 16 + nrow) * S2) * 2 + bko;
    }
    const uint32_t stA2 = sb + a2off + ((mw * 32 + lane) * S2) * 2 + nw * 128;
    const int r0 = lane >> 2;
    const int cq = 2 * (lane & 3);

    // ---- prefetch first tile's emb/x ----
    const int m = t >> 1, half = t & 1;
    const int tstep = 2 * gridDim.x;
    float pf_ev = 0.f; float2 pf_x = make_float2(0.f, 0.f);
    {
        int t0 = blockIdx.x * 2 + g;
        int gm = t0 * TM + m;
        if (gm >= Nq) gm = Nq - 1;
        pf_ev = __ldg(emb + gm);
        if (!half) pf_x = *(const float2*)(x + 2 * gm);
    }

    for (int tile = blockIdx.x * 2 + g; tile < ntiles; tile += tstep){
        const int base = tile * TM;
        GBAR(g);   // prior tile fully consumed A0/A2/red/xs

        // ---- build A0 (fp16 em, cols 0..31) + stage x rows ----
        {
            float ev = pf_ev;
            int e1 = (int)ev;
            int e2 = e1 + 1; if (e2 > E - 1) e2 = E - 1;
            float res = ev - (float)e1;
            char* A0c = smem + a0off + m * S0 * 2;
            const float4* p1 = (const float4*)(et + e1 * 32 + half * 16);
            const float4* p2 = (const float4*)(et + e2 * 32 + half * 16);
            if (!half) xs[m] = pf_x;
            #pragma unroll
            for (int q = 0; q < 4; q++){
                float4 u = p1[q], v = p2[q];
                float f0 = u.x + (v.x - u.x) * res;
                float f1 = u.y + (v.y - u.y) * res;
                float f2 = u.z + (v.z - u.z) * res;
                float f3 = u.w + (v.w - u.w) * res;
                int c = half * 16 + q * 4;
                *(uint32_t*)(A0c + c * 2)       = pk2(f0, f1);
                *(uint32_t*)(A0c + (c + 2) * 2) = pk2(f2, f3);
            }
            int tile2 = tile + tstep;
            if (tile2 < ntiles){
                int gm2 = tile2 * TM + m; if (gm2 >= Nq) gm2 = Nq - 1;
                pf_ev = __ldg(emb + gm2);
                if (!half) pf_x = *(const float2*)(x + 2 * gm2);
            }
        }
        GBAR(g);

        // ---- layer 1: A0[128x32] x W0em[32x128] (2 ksteps) ----
        float c[2][8][4];
        #pragma unroll
        for (int mi = 0; mi < 2; mi++)
            #pragma unroll
            for (int ni = 0; ni < 8; ni++)
                #pragma unroll
                for (int q = 0; q < 4; q++) c[mi][ni][q] = 0.f;
        gemm1p<2>(aB0, aB1, w0B, c);

        // ---- x-fold: c += x @ W0[0:2] (fp32 rank-2 update) ----
        #pragma unroll
        for (int mi = 0; mi < 2; mi++){
            float2 xa = xs[mw * 32 + mi * 16 + r0];
            float2 xb = xs[mw * 32 + mi * 16 + r0 + 8];
            #pragma unroll
            for (int ni = 0; ni < 8; ni++){
                int n = nw * 64 + ni * 8 + cq;
                float2 wa = *(const float2*)(xr0 + n);
                float2 wb = *(const float2*)(xr1 + n);
                c[mi][ni][0] += xa.x * wa.x + xa.y * wb.x;
                c[mi][ni][1] += xa.x * wa.y + xa.y * wb.y;
                c[mi][ni][2] += xb.x * wa.x + xb.y * wb.x;
                c[mi][ni][3] += xb.x * wa.y + xb.y * wb.y;
            }
        }

        // ---- epilogue 1: +b0, clip, fp16 -> stmatrix + register A-frags ----
        uint32_t areg[4][2][4];
        #pragma unroll
        for (int ni = 0; ni < 8; ni++){
            int n = nw * 64 + ni * 8 + cq;
            float2 bb = *(const float2*)(b0s + n);
            uint32_t q0 = pk2(clip01(c[0][ni][0] + bb.x), clip01(c[0][ni][1] + bb.y));
            uint32_t q1 = pk2(clip01(c[0][ni][2] + bb.x), clip01(c[0][ni][3] + bb.y));
            uint32_t q2 = pk2(clip01(c[1][ni][0] + bb.x), clip01(c[1][ni][1] + bb.y));
            uint32_t q3 = pk2(clip01(c[1][ni][2] + bb.x), clip01(c[1][ni][3] + bb.y));
            stsm4(stA2 + ni * 16, q0, q1, q2, q3);
            const int j = ni >> 1, hh = (ni & 1) * 2;
            areg[j][0][hh]     = q0;
            areg[j][0][hh + 1] = q1;
            areg[j][1][hh]     = q2;
            areg[j][1][hh + 1] = q3;
        }

        // ---- layer 2 phase A (pre-barrier): own 4 ksteps from registers ----
        #pragma unroll
        for (int mi = 0; mi < 2; mi++)
            #pragma unroll
            for (int ni = 0; ni < 8; ni++)
                #pragma unroll
                for (int q = 0; q < 4; q++) c[mi][ni][q] = 0.f;
        #pragma unroll
        for (int j = 0; j < 4; j++){
            const int ks = nw * 4 + j;
            uint32_t b[4][4];
            #pragma unroll
            for (int gg = 0; gg < 4; gg++) ldsm4(b[gg], w1B[gg] + 32 * ks);
            #pragma unroll
            for (int ni = 0; ni < 8; ni++){
                uint32_t b0v = b[ni >> 1][(ni & 1) * 2];
                uint32_t b1v = b[ni >> 1][(ni & 1) * 2 + 1];
                mma_f16(c[0][ni], areg[j][0], b0v, b1v);
                mma_f16(c[1][ni], areg[j][1], b0v, b1v);
            }
        }
        GBAR(g);   // partner's stmatrix now visible

        // ---- layer 2 phase B: partner's 4 ksteps from smem ----
        #pragma unroll
        for (int j = 0; j < 4; j++){
            const int ks = (nw ^ 1) * 4 + j;
            uint32_t a0[4], a1[4], b[4][4];
            ldsm4(a0, a2B0 + 32 * ks);
            ldsm4(a1, a2B1 + 32 * ks);
            #pragma unroll
            for (int gg = 0; gg < 4; gg++) ldsm4(b[gg], w1B[gg] + 32 * ks);
            #pragma unroll
            for (int ni = 0; ni < 8; ni++){
                uint32_t b0v = b[ni >> 1][(ni & 1) * 2];
                uint32_t b1v = b[ni >> 1][(ni & 1) * 2 + 1];
                mma_f16(c[0][ni], a0, b0v, b1v);
                mma_f16(c[1][ni], a1, b0v, b1v);
            }
        }

        // ---- epilogue 2: +b1, clip, dot W2, reduce, sigmoid ----
        {
            float acc[2][2] = {{0.f, 0.f}, {0.f, 0.f}};
            #pragma unroll
            for (int mi = 0; mi < 2; mi++)
                #pragma unroll
                for (int ni = 0; ni < 8; ni++){
                    int n = nw * 64 + ni * 8 + cq;
                    float2 bb = *(const float2*)(b1s + n);
                    float2 ww = *(const float2*)(w2s + n);
                    acc[mi][0] = fmaf(clip01(c[mi][ni][0] + bb.x), ww.x,
                                 fmaf(clip01(c[mi][ni][1] + bb.y), ww.y, acc[mi][0]));
                    acc[mi][1] = fmaf(clip01(c[mi][ni][2] + bb.x), ww.x,
                                 fmaf(clip01(c[mi][ni][3] + bb.y), ww.y, acc[mi][1]));
                }
            #pragma unroll
            for (int mi = 0; mi < 2; mi++)
                #pragma unroll
                for (int hb = 0; hb < 2; hb++){
                    float v = acc[mi][hb];
                    v += __shfl_xor_sync(0xffffffffu, v, 1);
                    v += __shfl_xor_sync(0xffffffffu, v, 2);
                    if ((lane & 3) == 0)
                        red[(mw * 32 + mi * 16 + r0 + hb * 8) * 2 + nw] = v;
                }
        }
        GBAR(g);

        if (t < TM){
            float z = b2v + red[t * 2] + red[t * 2 + 1];
            float o = 1.f / (1.f + __expf(-z));
            int gm = base + t;
            if (gm < Nq) out[gm] = o;
        }
    }
}

extern "C" void kernel_launch(void* const* d_in, const int* in_sizes, int n_in,
                              void* d_out, int out_size)
{
    const float* x   = (const float*)d_in[0];
    const float* emb = (const float*)d_in[1];
    const float* et  = (const float*)d_in[2];
    const float* W0  = (const float*)d_in[3];
    const float* b0  = (const float*)d_in[4];
    const float* W1  = (const float*)d_in[5];
    const float* b1  = (const float*)d_in[6];
    const float* W2  = (const float*)d_in[7];
    const float* b2  = (const float*)d_in[8];
    float* out = (float*)d_out;

    const int Nq = in_sizes[1];
    const int E  = in_sizes[2] / 32;
    const int ntiles = (Nq + TM - 1) / TM;

    cudaFuncSetAttribute(mlp_xf_kernel,
                         cudaFuncAttributeMaxDynamicSharedMemorySize, SMEM_BYTES);
    int sms = 148;
    cudaDeviceGetAttribute(&sms, cudaDevAttrMultiProcessorCount, 0);
    int grid = (ntiles + 1) / 2;
    if (grid > sms) grid = sms;

    mlp_xf_kernel<<<grid, THREADS, SMEM_BYTES>>>(
        x, emb, et, W0, b0, W1, b1, W2, b2, out, Nq, E, ntiles);
}

// round 15
// speedup vs baseline: 1.1837x; 1.1837x over previous
#include <cuda_runtime.h>
#include <cuda_fp16.h>
#include <cstdint>
#include <cstring>

#define THREADS 512
#define TM 128

#define S0  56    // A0 / W0 stride (halves) = 112B
#define S2  136   // A2 / W1 stride (halves) = 272B

// ---- smem byte layout: shared weights + per-group activation blocks ----
#define OFF_W0   0                       // 14336
#define OFF_W1   14336                   // 34816
#define GBASE    49152
#define GSTRIDE  50176                   // A0 14336 + A2 34816 + red 1024
#define OFF_B0S  (GBASE + 2*GSTRIDE)     // 149504
#define OFF_B1S  (OFF_B0S + 512)
#define OFF_W2S  (OFF_B1S + 512)
#define SMEM_BYTES (OFF_W2S + 512)       // 151040

__device__ __forceinline__ uint32_t s2u(const void* p){
    uint32_t a;
    asm("{ .reg .u64 t; cvta.to.shared.u64 t, %1; cvt.u32.u64 %0, t; }" : "=r"(a) : "l"(p));
    return a;
}
__device__ __forceinline__ void ldsm4(uint32_t r[4], uint32_t addr){
    asm volatile("ldmatrix.sync.aligned.m8n8.x4.shared.b16 {%0,%1,%2,%3}, [%4];"
                 : "=r"(r[0]), "=r"(r[1]), "=r"(r[2]), "=r"(r[3]) : "r"(addr));
}
__device__ __forceinline__ void stsm4(uint32_t addr, uint32_t r0, uint32_t r1,
                                      uint32_t r2, uint32_t r3){
    asm volatile("stmatrix.sync.aligned.m8n8.x4.shared.b16 [%0], {%1,%2,%3,%4};"
                 :: "r"(addr), "r"(r0), "r"(r1), "r"(r2), "r"(r3) : "memory");
}
__device__ __forceinline__ void mma_f16(float c[4], const uint32_t a[4],
                                        uint32_t b0, uint32_t b1){
    asm volatile("mma.sync.aligned.m16n8k16.row.col.f32.f16.f16.f32 "
                 "{%0,%1,%2,%3}, {%4,%5,%6,%7}, {%8,%9}, {%0,%1,%2,%3};"
                 : "+f"(c[0]), "+f"(c[1]), "+f"(c[2]), "+f"(c[3])
                 : "r"(a[0]), "r"(a[1]), "r"(a[2]), "r"(a[3]), "r"(b0), "r"(b1));
}
__device__ __forceinline__ float clip01(float v){ return fminf(fmaxf(v, 0.f), 1.f); }
__device__ __forceinline__ uint32_t pk2(float a, float b){
    __half2 h = __floats2half2_rn(a, b);
    uint32_t u; memcpy(&u, &h, 4); return u;
}
// per-group named barrier (ids 1,2), 256 threads each
#define GBAR(g) asm volatile("bar.sync %0, 256;" :: "r"((g) + 1) : "memory")

// single-pass fp16 GEMM (layer 1)
template<int KS>
__device__ __forceinline__ void gemm1p(uint32_t aB0, uint32_t aB1,
                                       const uint32_t bB[4], float c[2][8][4]){
    #pragma unroll
    for (int ks = 0; ks < KS; ks++){
        uint32_t a0[4], a1[4], b[4][4];
        ldsm4(a0, aB0 + 32 * ks);
        ldsm4(a1, aB1 + 32 * ks);
        #pragma unroll
        for (int gg = 0; gg < 4; gg++) ldsm4(b[gg], bB[gg] + 32 * ks);
        #pragma unroll
        for (int ni = 0; ni < 8; ni++){
            uint32_t b0v = b[ni >> 1][(ni & 1) * 2];
            uint32_t b1v = b[ni >> 1][(ni & 1) * 2 + 1];
            mma_f16(c[0][ni], a0, b0v, b1v);
            mma_f16(c[1][ni], a1, b0v, b1v);
        }
    }
}

__global__ void __launch_bounds__(THREADS, 1)
mlp_rf3_kernel(const float* __restrict__ x,
               const float* __restrict__ emb,
               const float* __restrict__ et,
               const float* __restrict__ W0,
               const float* __restrict__ b0,
               const float* __restrict__ W1,
               const float* __restrict__ b1,
               const float* __restrict__ W2,
               const float* __restrict__ b2,
               float* __restrict__ out,
               int Nq, int E, int ntiles)
{
    extern __shared__ __align__(1024) char smem[];
    const uint32_t sb = s2u(smem);
    const int tid = threadIdx.x;
    const int g   = tid >> 8;        // tile group 0/1
    const int t   = tid & 255;
    const int lane = t & 31, w = t >> 5;
    const int mw = w & 3, nw = w >> 2;

    const int a0off = GBASE + g * GSTRIDE;
    const int a2off = a0off + 14336;
    const int rdoff = a2off + 34816;

    // ---- zero W0 pad + both A0 buffers; load biases ----
    for (int i = tid * 16; i < 14336; i += THREADS * 16){
        *(float4*)(smem + OFF_W0 + i) = make_float4(0.f, 0.f, 0.f, 0.f);
        *(float4*)(smem + GBASE + i) = make_float4(0.f, 0.f, 0.f, 0.f);
        *(float4*)(smem + GBASE + GSTRIDE + i) = make_float4(0.f, 0.f, 0.f, 0.f);
    }
    if (tid < 128){
        ((float*)(smem + OFF_B0S))[tid] = b0[tid];
        ((float*)(smem + OFF_B1S))[tid] = b1[tid];
        ((float*)(smem + OFF_W2S))[tid] = W2[tid];
    }
    __syncthreads();

    // ---- stage W0^T / W1^T fp16 (shared by both groups) ----
    for (int i = tid; i < 34 * 128; i += THREADS){
        int k = i >> 7, n = i & 127;
        *(__half*)(smem + OFF_W0 + (n * S0 + k) * 2) = __float2half_rn(W0[i]);
    }
    for (int i = tid; i < 128 * 128; i += THREADS){
        int k = i >> 7, n = i & 127;
        *(__half*)(smem + OFF_W1 + (n * S2 + k) * 2) = __float2half_rn(W1[i]);
    }
    __syncthreads();

    const float b2v = __ldg(b2);
    const float* b0s = (const float*)(smem + OFF_B0S);
    const float* b1s = (const float*)(smem + OFF_B1S);
    const float* w2s = (const float*)(smem + OFF_W2S);
    float* red = (float*)(smem + rdoff);

    // ---- ldmatrix / stmatrix lane bases ----
    const uint32_t aB0 = sb + a0off + ((mw * 32 + (lane & 15)) * S0) * 2 + (lane >> 4) * 16;
    const uint32_t aB1 = aB0 + 16 * S0 * 2;
    const uint32_t a2B0 = sb + a2off + ((mw * 32 + (lane & 15)) * S2) * 2 + (lane >> 4) * 16;
    const uint32_t a2B1 = a2B0 + 16 * S2 * 2;
    const int nrow = (lane & 7) + ((lane >> 4) << 3);
    const int bko  = ((lane >> 3) & 1) * 16;
    uint32_t w0B[4], w1B[4];
    #pragma unroll
    for (int q = 0; q < 4; q++){
        w0B[q] = sb + OFF_W0 + ((nw * 64 + q * 16 + nrow) * S0) * 2 + bko;
        w1B[q] = sb + OFF_W1 + ((nw * 64 + q * 16 + nrow) * S2) * 2 + bko;
    }
    const uint32_t stA2 = sb + a2off + ((mw * 32 + lane) * S2) * 2 + nw * 128;
    const int r0 = lane >> 2;
    const int cq = 2 * (lane & 3);

    // ---- prefetch first tile's emb/x ----
    const int m = t >> 1, half = t & 1;
    const int tstep = 2 * gridDim.x;
    float pf_ev = 0.f; float2 pf_x = make_float2(0.f, 0.f);
    {
        int t0 = blockIdx.x * 2 + g;
        int gm = t0 * TM + m;
        if (gm >= Nq) gm = Nq - 1;
        pf_ev = __ldg(emb + gm);
        if (!half) pf_x = *(const float2*)(x + 2 * gm);
    }

    for (int tile = blockIdx.x * 2 + g; tile < ntiles; tile += tstep){
        const int base = tile * TM;
        // NOTE: no loop-top barrier. After the trailing GBAR of the previous
        // iteration, the only shared-state ops before the next GBAR are the
        // out-store (reads red; next red write is 2 barriers away) and this
        // A0 build (each thread writes only its own rows; prior A0 reads
        // finished in layer 1, three barriers ago). No hazard.

        // ---- build A0 (fp16, cols 0..33; 34..47 stay zero) ----
        {
            float ev = pf_ev;
            int e1 = (int)ev;
            int e2 = e1 + 1; if (e2 > E - 1) e2 = E - 1;
            float res = ev - (float)e1;
            char* A0c = smem + a0off + m * S0 * 2;
            const float4* p1 = (const float4*)(et + e1 * 32 + half * 16);
            const float4* p2 = (const float4*)(et + e2 * 32 + half * 16);
            if (!half) *(uint32_t*)(A0c) = pk2(pf_x.x, pf_x.y);
            #pragma unroll
            for (int q = 0; q < 4; q++){
                float4 u = p1[q], v = p2[q];
                float f0 = u.x + (v.x - u.x) * res;
                float f1 = u.y + (v.y - u.y) * res;
                float f2 = u.z + (v.z - u.z) * res;
                float f3 = u.w + (v.w - u.w) * res;
                int c = 2 + half * 16 + q * 4;
                *(uint32_t*)(A0c + c * 2)       = pk2(f0, f1);
                *(uint32_t*)(A0c + (c + 2) * 2) = pk2(f2, f3);
            }
            int tile2 = tile + tstep;
            if (tile2 < ntiles){
                int gm2 = tile2 * TM + m; if (gm2 >= Nq) gm2 = Nq - 1;
                pf_ev = __ldg(emb + gm2);
                if (!half) pf_x = *(const float2*)(x + 2 * gm2);
            }
        }
        GBAR(g);

        // ---- layer 1: A0[128x48] x W0[48x128] ----
        float c[2][8][4];
        #pragma unroll
        for (int mi = 0; mi < 2; mi++)
            #pragma unroll
            for (int ni = 0; ni < 8; ni++)
                #pragma unroll
                for (int q = 0; q < 4; q++) c[mi][ni][q] = 0.f;
        gemm1p<3>(aB0, aB1, w0B, c);

        // ---- epilogue 1: +b0, clip, fp16 -> stmatrix + register A-frags ----
        uint32_t areg[4][2][4];
        #pragma unroll
        for (int ni = 0; ni < 8; ni++){
            int n = nw * 64 + ni * 8 + cq;
            float2 bb = *(const float2*)(b0s + n);
            uint32_t q0 = pk2(clip01(c[0][ni][0] + bb.x), clip01(c[0][ni][1] + bb.y));
            uint32_t q1 = pk2(clip01(c[0][ni][2] + bb.x), clip01(c[0][ni][3] + bb.y));
            uint32_t q2 = pk2(clip01(c[1][ni][0] + bb.x), clip01(c[1][ni][1] + bb.y));
            uint32_t q3 = pk2(clip01(c[1][ni][2] + bb.x), clip01(c[1][ni][3] + bb.y));
            stsm4(stA2 + ni * 16, q0, q1, q2, q3);
            const int j = ni >> 1, hh = (ni & 1) * 2;
            areg[j][0][hh]     = q0;
            areg[j][0][hh + 1] = q1;
            areg[j][1][hh]     = q2;
            areg[j][1][hh + 1] = q3;
        }

        // ---- layer 2 phase A (pre-barrier): own 4 ksteps from registers ----
        #pragma unroll
        for (int mi = 0; mi < 2; mi++)
            #pragma unroll
            for (int ni = 0; ni < 8; ni++)
                #pragma unroll
                for (int q = 0; q < 4; q++) c[mi][ni][q] = 0.f;
        #pragma unroll
        for (int j = 0; j < 4; j++){
            const int ks = nw * 4 + j;
            uint32_t b[4][4];
            #pragma unroll
            for (int gg = 0; gg < 4; gg++) ldsm4(b[gg], w1B[gg] + 32 * ks);
            #pragma unroll
            for (int ni = 0; ni < 8; ni++){
                uint32_t b0v = b[ni >> 1][(ni & 1) * 2];
                uint32_t b1v = b[ni >> 1][(ni & 1) * 2 + 1];
                mma_f16(c[0][ni], areg[j][0], b0v, b1v);
                mma_f16(c[1][ni], areg[j][1], b0v, b1v);
            }
        }
        GBAR(g);   // partner's stmatrix now visible

        // ---- layer 2 phase B: partner's 4 ksteps from smem ----
        #pragma unroll
        for (int j = 0; j < 4; j++){
            const int ks = (nw ^ 1) * 4 + j;
            uint32_t a0[4], a1[4], b[4][4];
            ldsm4(a0, a2B0 + 32 * ks);
            ldsm4(a1, a2B1 + 32 * ks);
            #pragma unroll
            for (int gg = 0; gg < 4; gg++) ldsm4(b[gg], w1B[gg] + 32 * ks);
            #pragma unroll
            for (int ni = 0; ni < 8; ni++){
                uint32_t b0v = b[ni >> 1][(ni & 1) * 2];
                uint32_t b1v = b[ni >> 1][(ni & 1) * 2 + 1];
                mma_f16(c[0][ni], a0, b0v, b1v);
                mma_f16(c[1][ni], a1, b0v, b1v);
            }
        }

        // ---- epilogue 2: +b1, clip, dot W2, reduce, sigmoid ----
        {
            float acc[2][2] = {{0.f, 0.f}, {0.f, 0.f}};
            #pragma unroll
            for (int mi = 0; mi < 2; mi++)
                #pragma unroll
                for (int ni = 0; ni < 8; ni++){
                    int n = nw * 64 + ni * 8 + cq;
                    float2 bb = *(const float2*)(b1s + n);
                    float2 ww = *(const float2*)(w2s + n);
                    acc[mi][0] = fmaf(clip01(c[mi][ni][0] + bb.x), ww.x,
                                 fmaf(clip01(c[mi][ni][1] + bb.y), ww.y, acc[mi][0]));
                    acc[mi][1] = fmaf(clip01(c[mi][ni][2] + bb.x), ww.x,
                                 fmaf(clip01(c[mi][ni][3] + bb.y), ww.y, acc[mi][1]));
                }
            #pragma unroll
            for (int mi = 0; mi < 2; mi++)
                #pragma unroll
                for (int hb = 0; hb < 2; hb++){
                    float v = acc[mi][hb];
                    v += __shfl_xor_sync(0xffffffffu, v, 1);
                    v += __shfl_xor_sync(0xffffffffu, v, 2);
                    if ((lane & 3) == 0)
                        red[(mw * 32 + mi * 16 + r0 + hb * 8) * 2 + nw] = v;
                }
        }
        GBAR(g);

        if (t < TM){
            float z = b2v + red[t * 2] + red[t * 2 + 1];
            float o = 1.f / (1.f + __expf(-z));
            int gm = base + t;
            if (gm < Nq) out[gm] = o;
        }
    }
}

extern "C" void kernel_launch(void* const* d_in, const int* in_sizes, int n_in,
                              void* d_out, int out_size)
{
    const float* x   = (const float*)d_in[0];
    const float* emb = (const float*)d_in[1];
    const float* et  = (const float*)d_in[2];
    const float* W0  = (const float*)d_in[3];
    const float* b0  = (const float*)d_in[4];
    const float* W1  = (const float*)d_in[5];
    const float* b1  = (const float*)d_in[6];
    const float* W2  = (const float*)d_in[7];
    const float* b2  = (const float*)d_in[8];
    float* out = (float*)d_out;

    const int Nq = in_sizes[1];
    const int E  = in_sizes[2] / 32;
    const int ntiles = (Nq + TM - 1) / TM;

    cudaFuncSetAttribute(mlp_rf3_kernel,
                         cudaFuncAttributeMaxDynamicSharedMemorySize, SMEM_BYTES);
    int sms = 148;
    cudaDeviceGetAttribute(&sms, cudaDevAttrMultiProcessorCount, 0);
    int grid = (ntiles + 1) / 2;
    if (grid > sms) grid = sms;

    mlp_rf3_kernel<<<grid, THREADS, SMEM_BYTES>>>(
        x, emb, et, W0, b0, W1, b1, W2, b2, out, Nq, E, ntiles);
}